// round 6
// baseline (speedup 1.0000x reference)
#include <cuda_runtime.h>
#include <cuda_fp16.h>
#include <cstdint>

#define BN     50000
#define NBR    4
#define DD     32
#define CC     128          // NBR*DD
#define MM     256
#define NODES  (BN + MM)    // 50256
#define CAPR   128          // per-batch-row bucket capacity (mean ~40)

// scratch (static device globals — no allocation)
__device__ __half g_h16[(size_t)NODES * CC];   // 12.9MB (Y path only)
__device__ float  g_out[(size_t)BN * CC];
__device__ int    g_cnt[BN];
__device__ int2   g_ent[(size_t)BN * CAPR];    // (src_row, w_bits) per batch-dst
__device__ float  g_vq32[MM * CC];             // vq_grad re-laid [m][b*32+e], 128KB
__device__ float  g_vsum[(size_t)BN * CC];     // per-row sum w*vq (fp32)
__device__ float  g_info;

// packed fp32x2 FMA (Blackwell): d = a*b + c elementwise on 2 floats
#define FMA2(d, a, b, c) \
    asm("fma.rn.f32x2 %0, %1, %2, %3;" : "=l"(d) : "l"(a), "l"(b), "l"(c))
#define PACK_DUP(out, x) \
    asm("mov.b64 %0, {%1, %1};" : "=l"(out) : "r"(__float_as_int(x)))
#define UNPACK2(lo, hi, in) \
    asm("mov.b64 {%0, %1}, %2;" : "=r"(lo), "=r"(hi) : "l"(in))

// ---------------------------------------------------------------------------
// prep: zero counters/info + relayout vq_grad [b][m][e] -> [m][b*32+e]
// ---------------------------------------------------------------------------
__global__ void prep_kernel(const float* __restrict__ vq_grad) {
    const int idx = blockIdx.x * blockDim.x + threadIdx.x;
    if (idx < NBR * MM * DD) {
        const int b = idx >> 13;
        const int m = (idx >> 5) & (MM - 1);
        const int e = idx & 31;
        g_vq32[m * CC + b * DD + e] = vq_grad[idx];
    }
    if (idx < BN) g_cnt[idx] = 0;
    if (idx == 0) g_info = 0.0f;
}

// ---------------------------------------------------------------------------
// Bucket all edges by destination batch row. 4 edges per thread (strided
// quarters), front-batched loads so the ~318-cyc atomic returns overlap.
// Guard t < q: threads beyond the quarter-stride would re-process edges.
// ---------------------------------------------------------------------------
__global__ void fill_dst_kernel(const int* __restrict__ sbb, const int* __restrict__ dbb,
                                const float* __restrict__ wbb,
                                const int* __restrict__ sbm, const int* __restrict__ dbm,
                                const float* __restrict__ wbm,
                                const int* __restrict__ cidx, int Ebb, int Etot) {
    const int t = blockIdx.x * blockDim.x + threadIdx.x;
    const int q = (Etot + 3) >> 2;      // quarter stride (coalesced groups)
    if (t >= q) return;                 // <-- fix: no duplicate coverage
    int  r[4], s[4]; float w[4]; bool v[4];
    #pragma unroll
    for (int j = 0; j < 4; j++) {
        const int i = t + j * q;
        v[j] = (i < Etot);
        if (v[j]) {
            if (i < Ebb) { r[j] = dbb[i]; s[j] = sbb[i]; w[j] = wbb[i]; }
            else { const int k = i - Ebb; r[j] = dbm[k]; s[j] = BN + cidx[sbm[k]]; w[j] = wbm[k]; }
        }
    }
    int pos[4];
    #pragma unroll
    for (int j = 0; j < 4; j++)
        if (v[j]) pos[j] = atomicAdd(&g_cnt[r[j]], 1);
    #pragma unroll
    for (int j = 0; j < 4; j++)
        if (v[j] && pos[j] < CAPR)
            g_ent[(size_t)r[j] * CAPR + pos[j]] = make_int2(s[j], __float_as_int(w[j]));
}

// ---------------------------------------------------------------------------
// vsum[r] = sum over bucket entries with src >= BN of w * vq32[src-BN].
// Branch-free (bb entries map to c=0, w=0), 4-wide chunk with 1-chunk
// lookahead so the L2 entry loads overlap; vq loads are L1-hits.
// ---------------------------------------------------------------------------
__device__ __forceinline__ void vs_proc(float4& vs, int2 E, int lane) {
    int c = E.x - BN;
    float w = __int_as_float(E.y);
    if (c < 0) { c = 0; w = 0.0f; }
    const float4 qv = ((const float4*)(g_vq32 + (size_t)c * CC))[lane];
    vs.x = fmaf(w, qv.x, vs.x); vs.y = fmaf(w, qv.y, vs.y);
    vs.z = fmaf(w, qv.z, vs.z); vs.w = fmaf(w, qv.w, vs.w);
}

__global__ void vsum_kernel() {
    const int gw   = (blockIdx.x * blockDim.x + threadIdx.x) >> 5;
    const int lane = threadIdx.x & 31;
    if (gw >= BN) return;
    int n = g_cnt[gw]; if (n > CAPR) n = CAPR;

    const int2* ep = g_ent + (size_t)gw * CAPR;
    const int2 Z = make_int2(BN, 0);    // c=0, w=0 -> no-op
    float4 vs = make_float4(0.f, 0.f, 0.f, 0.f);

    int2 c0 = (0 < n) ? ep[0] : Z;
    int2 c1 = (1 < n) ? ep[1] : Z;
    int2 c2 = (2 < n) ? ep[2] : Z;
    int2 c3 = (3 < n) ? ep[3] : Z;
    for (int e = 0; e < n; e += 4) {
        const int2 n0 = (e + 4 < n) ? ep[e + 4] : Z;
        const int2 n1 = (e + 5 < n) ? ep[e + 5] : Z;
        const int2 n2 = (e + 6 < n) ? ep[e + 6] : Z;
        const int2 n3 = (e + 7 < n) ? ep[e + 7] : Z;
        vs_proc(vs, c0, lane); vs_proc(vs, c1, lane);
        vs_proc(vs, c2, lane); vs_proc(vs, c3, lane);
        c0 = n0; c1 = n1; c2 = n2; c3 = n3;
    }
    ((float4*)(g_vsum + (size_t)gw * CC))[lane] = vs;
}

// ---------------------------------------------------------------------------
// h16[node, b*32+e] = sum_d Xin[node, b*32+d] * W_conv[b, d, e]   (fp16 store)
// PLUS exact fp32 info partial: dot(h32_row, vsum_row) while h32 is live.
// ---------------------------------------------------------------------------
__global__ void compute_h_kernel(const float* __restrict__ X,
                                 const float* __restrict__ codebook,
                                 const float* __restrict__ W_conv,
                                 const float* __restrict__ wr_p) {
    __shared__ float Ws[NBR * DD * DD];   // 16KB
    for (int i = threadIdx.x; i < NBR * DD * DD; i += blockDim.x)
        Ws[i] = W_conv[i];
    __syncthreads();

    const float wr = wr_p[0];
    const int gw   = (blockIdx.x * blockDim.x + threadIdx.x) >> 5;
    const int lane = threadIdx.x & 31;
    const int b    = gw & 3;
    const int row  = (gw >> 2) * 32 + lane;

    float x[DD];
    bool active = (row < NODES);
    if (active) {
        if (row < BN) {
            const float4* p = (const float4*)(X + (size_t)row * CC + b * DD);
            #pragma unroll
            for (int i = 0; i < 8; i++) {
                float4 v = p[i];
                x[4*i+0] = v.x; x[4*i+1] = v.y; x[4*i+2] = v.z; x[4*i+3] = v.w;
            }
        } else {
            const int m = row - BN;
            const float4* p = (const float4*)(codebook + ((size_t)b * MM + m) * DD);
            #pragma unroll
            for (int i = 0; i < 8; i++) {
                float4 v = p[i];
                x[4*i+0] = v.x * wr; x[4*i+1] = v.y * wr;
                x[4*i+2] = v.z * wr; x[4*i+3] = v.w * wr;
            }
        }
    } else {
        #pragma unroll
        for (int i = 0; i < DD; i++) x[i] = 0.0f;
    }

    float acc[DD];
    #pragma unroll
    for (int e = 0; e < DD; e++) acc[e] = 0.0f;
    #pragma unroll
    for (int d = 0; d < DD; d++) {
        const float xd = x[d];
        const float* wrow = &Ws[b * (DD*DD) + d * DD];
        #pragma unroll
        for (int e = 0; e < DD; e++)
            acc[e] = fmaf(xd, wrow[e], acc[e]);
    }

    // info partial: exact fp32 dot of this h-row-segment with vsum[row] segment
    float p = 0.0f;
    if (active && row < BN) {
        const float4* vp = (const float4*)(g_vsum + (size_t)row * CC + b * DD);
        #pragma unroll
        for (int i = 0; i < 8; i++) {
            const float4 v = vp[i];
            p = fmaf(acc[4*i+0], v.x, p);
            p = fmaf(acc[4*i+1], v.y, p);
            p = fmaf(acc[4*i+2], v.z, p);
            p = fmaf(acc[4*i+3], v.w, p);
        }
    }
    #pragma unroll
    for (int s = 16; s > 0; s >>= 1)
        p += __shfl_xor_sync(0xFFFFFFFF, p, s);
    if (lane == 0 && p != 0.0f) atomicAdd(&g_info, p);

    if (active) {
        uint4 pk[4];
        #pragma unroll
        for (int i = 0; i < 4; i++) {
            __half2 h0 = __floats2half2_rn(acc[8*i+0], acc[8*i+1]);
            __half2 h1 = __floats2half2_rn(acc[8*i+2], acc[8*i+3]);
            __half2 h2 = __floats2half2_rn(acc[8*i+4], acc[8*i+5]);
            __half2 h3 = __floats2half2_rn(acc[8*i+6], acc[8*i+7]);
            pk[i].x = *(unsigned*)&h0; pk[i].y = *(unsigned*)&h1;
            pk[i].z = *(unsigned*)&h2; pk[i].w = *(unsigned*)&h3;
        }
        uint4* o = (uint4*)(g_h16 + (size_t)row * CC + b * DD);
        #pragma unroll
        for (int i = 0; i < 4; i++) o[i] = pk[i];
    }
}

// ---------------------------------------------------------------------------
// Gather: one warp per batch row. out[r] = b_conv + sum w * h16[src].
// ---------------------------------------------------------------------------
__device__ __forceinline__ void fma_h16(float4& acc, int2 ent, uint2 hv) {
    const float w = __int_as_float(ent.y);
    const float2 f0 = __half22float2(*(const __half2*)&hv.x);
    const float2 f1 = __half22float2(*(const __half2*)&hv.y);
    acc.x = fmaf(w, f0.x, acc.x); acc.y = fmaf(w, f0.y, acc.y);
    acc.z = fmaf(w, f1.x, acc.z); acc.w = fmaf(w, f1.y, acc.w);
}

__global__ void gather_kernel(const float* __restrict__ b_conv) {
    const int gw   = (blockIdx.x * blockDim.x + threadIdx.x) >> 5;
    const int lane = threadIdx.x & 31;
    if (gw >= BN) return;
    int n = g_cnt[gw]; if (n > CAPR) n = CAPR;

    float4 acc = ((const float4*)b_conv)[lane];
    const int2* ep = g_ent + (size_t)gw * CAPR;
    const int2 Z = make_int2(0, 0);   // w bits == 0.0f

    int2 eA = (n > 0) ? ep[0] : Z;
    int2 eB = (n > 1) ? ep[1] : Z;
    uint2 hA = ((const uint2*)(g_h16 + (size_t)eA.x * CC))[lane];
    uint2 hB = ((const uint2*)(g_h16 + (size_t)eB.x * CC))[lane];

    for (int e = 0; e < n; e += 2) {
        const int2 nA = (e + 2 < n) ? ep[e + 2] : Z;
        const int2 nB = (e + 3 < n) ? ep[e + 3] : Z;
        const uint2 nhA = ((const uint2*)(g_h16 + (size_t)nA.x * CC))[lane];
        const uint2 nhB = ((const uint2*)(g_h16 + (size_t)nB.x * CC))[lane];
        fma_h16(acc, eA, hA);
        fma_h16(acc, eB, hB);
        eA = nA; hA = nhA; eB = nB; hB = nhB;
    }
    ((float4*)(g_out + (size_t)gw * CC))[lane] = acc;
}

// ---------------------------------------------------------------------------
// finalize: out_scalar = (g_info + sum b_conv[col]*vq[b,m,e]) * wr
// ---------------------------------------------------------------------------
__global__ void finalize_kernel(const float* __restrict__ vq_grad,
                                const float* __restrict__ b_conv,
                                const float* __restrict__ wr_p,
                                float* __restrict__ out_scalar) {
    __shared__ float red[256];
    float s = 0.0f;
    for (int idx = threadIdx.x; idx < NBR * MM * DD; idx += 256) {
        const int b = idx >> 13;
        const int e = idx & 31;
        s += b_conv[b * DD + e] * vq_grad[idx];
    }
    red[threadIdx.x] = s;
    __syncthreads();
    for (int st = 128; st > 0; st >>= 1) {
        if (threadIdx.x < st) red[threadIdx.x] += red[threadIdx.x + st];
        __syncthreads();
    }
    if (threadIdx.x == 0) *out_scalar = (red[0] + g_info) * wr_p[0];
}

// ---------------------------------------------------------------------------
// Y[r,c] = sum_k out[r,k]*W_fc[k,c] + b_fc[c] + X_B[r,c]
// Packed fp32x2 FMA: thread = 2 rows x 4 cols = 4 f32x2 accumulators.
// ---------------------------------------------------------------------------
__global__ void y_kernel(const float* __restrict__ X,
                         const float* __restrict__ W_fc,
                         const float* __restrict__ b_fc,
                         float* __restrict__ Y) {
    __shared__ float Xs[16][CC];
    const int row0 = blockIdx.x * 16;
    for (int i = threadIdx.x; i < 16 * CC; i += 256) {
        const int r = i >> 7, c = i & 127;
        Xs[r][c] = g_out[(size_t)(row0 + r) * CC + c];
    }
    __syncthreads();

    const int cg = threadIdx.x & 31;
    const int rg = threadIdx.x >> 5;
    const ulonglong2* W2 = (const ulonglong2*)W_fc;   // 32 x (2 packed pairs) per k-row

    unsigned long long a00 = 0ull, a01 = 0ull, a10 = 0ull, a11 = 0ull;

    #pragma unroll 4
    for (int k = 0; k < CC; k++) {
        const ulonglong2 wp = W2[k * 32 + cg];
        unsigned long long px0, px1;
        PACK_DUP(px0, Xs[rg * 2 + 0][k]);
        PACK_DUP(px1, Xs[rg * 2 + 1][k]);
        FMA2(a00, px0, wp.x, a00);
        FMA2(a01, px0, wp.y, a01);
        FMA2(a10, px1, wp.x, a10);
        FMA2(a11, px1, wp.y, a11);
    }

    const float4 bf = ((const float4*)b_fc)[cg];
    int lx, ly, lz, lw;
    {
        const int row = row0 + rg * 2;
        const float4 xb = ((const float4*)(X + (size_t)row * CC))[cg];
        UNPACK2(lx, ly, a00); UNPACK2(lz, lw, a01);
        ((float4*)(Y + (size_t)row * CC))[cg] = make_float4(
            __int_as_float(lx) + bf.x + xb.x, __int_as_float(ly) + bf.y + xb.y,
            __int_as_float(lz) + bf.z + xb.z, __int_as_float(lw) + bf.w + xb.w);
    }
    {
        const int row = row0 + rg * 2 + 1;
        const float4 xb = ((const float4*)(X + (size_t)row * CC))[cg];
        UNPACK2(lx, ly, a10); UNPACK2(lz, lw, a11);
        ((float4*)(Y + (size_t)row * CC))[cg] = make_float4(
            __int_as_float(lx) + bf.x + xb.x, __int_as_float(ly) + bf.y + xb.y,
            __int_as_float(lz) + bf.z + xb.z, __int_as_float(lw) + bf.w + xb.w);
    }
}

// ---------------------------------------------------------------------------
extern "C" void kernel_launch(void* const* d_in, const int* in_sizes, int n_in,
                              void* d_out, int out_size) {
    const float* X_B      = (const float*)d_in[0];
    const int*   esrc_bb  = (const int*)  d_in[1];
    const int*   edst_bb  = (const int*)  d_in[2];
    const float* ew_bb    = (const float*)d_in[3];
    const int*   esrc_bm  = (const int*)  d_in[4];
    const int*   edst_bm  = (const int*)  d_in[5];
    const float* ew_bm    = (const float*)d_in[6];
    const int*   c_idx    = (const int*)  d_in[7];
    const float* wr       = (const float*)d_in[8];
    const float* codebook = (const float*)d_in[9];
    const float* vq_grad  = (const float*)d_in[10];
    const float* W_conv   = (const float*)d_in[11];
    const float* b_conv   = (const float*)d_in[12];
    const float* W_fc     = (const float*)d_in[13];
    const float* b_fc     = (const float*)d_in[14];
    float* out = (float*)d_out;

    const int Ebb  = in_sizes[1];
    const int Ebm  = in_sizes[4];
    const int Etot = Ebb + Ebm;

    prep_kernel<<<(BN + 255) / 256, 256>>>(vq_grad);
    {
        const int threads = (Etot + 3) / 4;
        fill_dst_kernel<<<(threads + 255) / 256, 256>>>(esrc_bb, edst_bb, ew_bb,
                                                        esrc_bm, edst_bm, ew_bm,
                                                        c_idx, Ebb, Etot);
    }
    vsum_kernel<<<(BN * 32 + 255) / 256, 256>>>();
    {
        const int warps = ((NODES + 31) / 32) * NBR;
        compute_h_kernel<<<(warps * 32 + 255) / 256, 256>>>(X_B, codebook, W_conv, wr);
    }
    gather_kernel<<<(BN * 32 + 255) / 256, 256>>>(b_conv);
    finalize_kernel<<<1, 256>>>(vq_grad, b_conv, wr, out + (out_size - 1));
    y_kernel<<<BN / 16, 256>>>(X_B, W_fc, b_fc, out);
}

// round 7
// speedup vs baseline: 1.0194x; 1.0194x over previous
#include <cuda_runtime.h>
#include <cuda_fp16.h>
#include <cstdint>

#define BN     50000
#define NBR    4
#define DD     32
#define CC     128          // NBR*DD
#define MM     256
#define NODES  (BN + MM)    // 50256
#define CAPR   128          // per-batch-row bucket capacity (mean ~40)

// scratch (static device globals — no allocation)
__device__ __half g_h16[(size_t)NODES * CC];   // 12.9MB (Y path only)
__device__ float  g_out[(size_t)BN * CC];
__device__ int    g_cnt[BN];
__device__ int2   g_ent[(size_t)BN * CAPR];    // (src_row, w_bits) per batch-dst
__device__ float  g_vq32[MM * CC];             // vq_grad re-laid [m][b*32+e], 128KB
__device__ float  g_vsum[(size_t)BN * CC];     // per-row sum w*vq (fp32)
__device__ float  g_info;

// ---------------------------------------------------------------------------
// prep: zero counters/info + relayout vq_grad [b][m][e] -> [m][b*32+e]
// ---------------------------------------------------------------------------
__global__ void prep_kernel(const float* __restrict__ vq_grad) {
    const int idx = blockIdx.x * blockDim.x + threadIdx.x;
    if (idx < NBR * MM * DD) {
        const int b = idx >> 13;
        const int m = (idx >> 5) & (MM - 1);
        const int e = idx & 31;
        g_vq32[m * CC + b * DD + e] = vq_grad[idx];
    }
    if (idx < BN) g_cnt[idx] = 0;
    if (idx == 0) g_info = 0.0f;
}

// ---------------------------------------------------------------------------
// Bucket all edges by destination batch row (1 edge per thread — max warps
// in flight to hide the ~318-cyc atomic).
// ---------------------------------------------------------------------------
__global__ void fill_dst_kernel(const int* __restrict__ sbb, const int* __restrict__ dbb,
                                const float* __restrict__ wbb,
                                const int* __restrict__ sbm, const int* __restrict__ dbm,
                                const float* __restrict__ wbm,
                                const int* __restrict__ cidx, int Ebb, int Etot) {
    const int i = blockIdx.x * blockDim.x + threadIdx.x;
    if (i >= Etot) return;
    int r, s; float w;
    if (i < Ebb) { r = dbb[i]; s = sbb[i]; w = wbb[i]; }
    else { const int j = i - Ebb; r = dbm[j]; s = BN + cidx[sbm[j]]; w = wbm[j]; }
    const int pos = atomicAdd(&g_cnt[r], 1);
    if (pos < CAPR)
        g_ent[(size_t)r * CAPR + pos] = make_int2(s, __float_as_int(w));
}

// ---------------------------------------------------------------------------
// vsum[r] = sum over bucket entries with src >= BN of w * vq32[src-BN].
// Branch-free (bb entries map to c=0, w=0), 4-wide with 1-chunk lookahead.
// ---------------------------------------------------------------------------
__device__ __forceinline__ void vs_proc(float4& vs, int2 E, int lane) {
    int c = E.x - BN;
    float w = __int_as_float(E.y);
    if (c < 0) { c = 0; w = 0.0f; }
    const float4 qv = ((const float4*)(g_vq32 + (size_t)c * CC))[lane];
    vs.x = fmaf(w, qv.x, vs.x); vs.y = fmaf(w, qv.y, vs.y);
    vs.z = fmaf(w, qv.z, vs.z); vs.w = fmaf(w, qv.w, vs.w);
}

__global__ void vsum_kernel() {
    const int gw   = (blockIdx.x * blockDim.x + threadIdx.x) >> 5;
    const int lane = threadIdx.x & 31;
    if (gw >= BN) return;
    int n = g_cnt[gw]; if (n > CAPR) n = CAPR;

    const int2* ep = g_ent + (size_t)gw * CAPR;
    const int2 Z = make_int2(BN, 0);    // c=0, w=0 -> no-op
    float4 vs = make_float4(0.f, 0.f, 0.f, 0.f);

    int2 c0 = (0 < n) ? ep[0] : Z;
    int2 c1 = (1 < n) ? ep[1] : Z;
    int2 c2 = (2 < n) ? ep[2] : Z;
    int2 c3 = (3 < n) ? ep[3] : Z;
    for (int e = 0; e < n; e += 4) {
        const int2 n0 = (e + 4 < n) ? ep[e + 4] : Z;
        const int2 n1 = (e + 5 < n) ? ep[e + 5] : Z;
        const int2 n2 = (e + 6 < n) ? ep[e + 6] : Z;
        const int2 n3 = (e + 7 < n) ? ep[e + 7] : Z;
        vs_proc(vs, c0, lane); vs_proc(vs, c1, lane);
        vs_proc(vs, c2, lane); vs_proc(vs, c3, lane);
        c0 = n0; c1 = n1; c2 = n2; c3 = n3;
    }
    ((float4*)(g_vsum + (size_t)gw * CC))[lane] = vs;
}

// ---------------------------------------------------------------------------
// h16[node, b*32+e] = sum_d Xin[node, b*32+d] * W_conv[b, d, e]   (fp16 store)
// PLUS exact fp32 info partial: dot(h32_row, vsum_row) while h32 is live.
// e-loop split into two 16-col passes to cut register pressure (acc 32->16).
// ---------------------------------------------------------------------------
__global__ void compute_h_kernel(const float* __restrict__ X,
                                 const float* __restrict__ codebook,
                                 const float* __restrict__ W_conv,
                                 const float* __restrict__ wr_p) {
    __shared__ float Ws[NBR * DD * DD];   // 16KB
    for (int i = threadIdx.x; i < NBR * DD * DD; i += blockDim.x)
        Ws[i] = W_conv[i];
    __syncthreads();

    const float wr = wr_p[0];
    const int gw   = (blockIdx.x * blockDim.x + threadIdx.x) >> 5;
    const int lane = threadIdx.x & 31;
    const int b    = gw & 3;
    const int row  = (gw >> 2) * 32 + lane;

    float x[DD];
    const bool active = (row < NODES);
    if (active) {
        if (row < BN) {
            const float4* p = (const float4*)(X + (size_t)row * CC + b * DD);
            #pragma unroll
            for (int i = 0; i < 8; i++) {
                float4 v = p[i];
                x[4*i+0] = v.x; x[4*i+1] = v.y; x[4*i+2] = v.z; x[4*i+3] = v.w;
            }
        } else {
            const int m = row - BN;
            const float4* p = (const float4*)(codebook + ((size_t)b * MM + m) * DD);
            #pragma unroll
            for (int i = 0; i < 8; i++) {
                float4 v = p[i];
                x[4*i+0] = v.x * wr; x[4*i+1] = v.y * wr;
                x[4*i+2] = v.z * wr; x[4*i+3] = v.w * wr;
            }
        }
    } else {
        #pragma unroll
        for (int i = 0; i < DD; i++) x[i] = 0.0f;
    }

    float p = 0.0f;   // info partial
    const bool doinfo = active && (row < BN);

    #pragma unroll
    for (int half = 0; half < 2; half++) {
        float acc[16];
        #pragma unroll
        for (int e = 0; e < 16; e++) acc[e] = 0.0f;
        #pragma unroll
        for (int d = 0; d < DD; d++) {
            const float xd = x[d];
            const float* wrow = &Ws[b * (DD*DD) + d * DD + half * 16];
            #pragma unroll
            for (int e = 0; e < 16; e++)
                acc[e] = fmaf(xd, wrow[e], acc[e]);
        }

        if (doinfo) {
            const float4* vp = (const float4*)(g_vsum + (size_t)row * CC + b * DD + half * 16);
            #pragma unroll
            for (int i = 0; i < 4; i++) {
                const float4 v = vp[i];
                p = fmaf(acc[4*i+0], v.x, p);
                p = fmaf(acc[4*i+1], v.y, p);
                p = fmaf(acc[4*i+2], v.z, p);
                p = fmaf(acc[4*i+3], v.w, p);
            }
        }

        if (active) {
            uint4 pk[2];
            #pragma unroll
            for (int i = 0; i < 2; i++) {
                __half2 h0 = __floats2half2_rn(acc[8*i+0], acc[8*i+1]);
                __half2 h1 = __floats2half2_rn(acc[8*i+2], acc[8*i+3]);
                __half2 h2 = __floats2half2_rn(acc[8*i+4], acc[8*i+5]);
                __half2 h3 = __floats2half2_rn(acc[8*i+6], acc[8*i+7]);
                pk[i].x = *(unsigned*)&h0; pk[i].y = *(unsigned*)&h1;
                pk[i].z = *(unsigned*)&h2; pk[i].w = *(unsigned*)&h3;
            }
            uint4* o = (uint4*)(g_h16 + (size_t)row * CC + b * DD + half * 16);
            o[0] = pk[0];
            o[1] = pk[1];
        }
    }

    #pragma unroll
    for (int s = 16; s > 0; s >>= 1)
        p += __shfl_xor_sync(0xFFFFFFFF, p, s);
    if (lane == 0 && p != 0.0f) atomicAdd(&g_info, p);
}

// ---------------------------------------------------------------------------
// Gather: one warp per batch row. out[r] = b_conv + sum w * h16[src].
// ---------------------------------------------------------------------------
__device__ __forceinline__ void fma_h16(float4& acc, int2 ent, uint2 hv) {
    const float w = __int_as_float(ent.y);
    const float2 f0 = __half22float2(*(const __half2*)&hv.x);
    const float2 f1 = __half22float2(*(const __half2*)&hv.y);
    acc.x = fmaf(w, f0.x, acc.x); acc.y = fmaf(w, f0.y, acc.y);
    acc.z = fmaf(w, f1.x, acc.z); acc.w = fmaf(w, f1.y, acc.w);
}

__global__ void gather_kernel(const float* __restrict__ b_conv) {
    const int gw   = (blockIdx.x * blockDim.x + threadIdx.x) >> 5;
    const int lane = threadIdx.x & 31;
    if (gw >= BN) return;
    int n = g_cnt[gw]; if (n > CAPR) n = CAPR;

    float4 acc = ((const float4*)b_conv)[lane];
    const int2* ep = g_ent + (size_t)gw * CAPR;
    const int2 Z = make_int2(0, 0);   // w bits == 0.0f

    int2 eA = (n > 0) ? ep[0] : Z;
    int2 eB = (n > 1) ? ep[1] : Z;
    uint2 hA = ((const uint2*)(g_h16 + (size_t)eA.x * CC))[lane];
    uint2 hB = ((const uint2*)(g_h16 + (size_t)eB.x * CC))[lane];

    for (int e = 0; e < n; e += 2) {
        const int2 nA = (e + 2 < n) ? ep[e + 2] : Z;
        const int2 nB = (e + 3 < n) ? ep[e + 3] : Z;
        const uint2 nhA = ((const uint2*)(g_h16 + (size_t)nA.x * CC))[lane];
        const uint2 nhB = ((const uint2*)(g_h16 + (size_t)nB.x * CC))[lane];
        fma_h16(acc, eA, hA);
        fma_h16(acc, eB, hB);
        eA = nA; hA = nhA; eB = nB; hB = nhB;
    }
    ((float4*)(g_out + (size_t)gw * CC))[lane] = acc;
}

// ---------------------------------------------------------------------------
// finalize: out_scalar = (g_info + sum b_conv[col]*vq[b,m,e]) * wr
// ---------------------------------------------------------------------------
__global__ void finalize_kernel(const float* __restrict__ vq_grad,
                                const float* __restrict__ b_conv,
                                const float* __restrict__ wr_p,
                                float* __restrict__ out_scalar) {
    __shared__ float red[256];
    float s = 0.0f;
    for (int idx = threadIdx.x; idx < NBR * MM * DD; idx += 256) {
        const int b = idx >> 13;
        const int e = idx & 31;
        s += b_conv[b * DD + e] * vq_grad[idx];
    }
    red[threadIdx.x] = s;
    __syncthreads();
    for (int st = 128; st > 0; st >>= 1) {
        if (threadIdx.x < st) red[threadIdx.x] += red[threadIdx.x + st];
        __syncthreads();
    }
    if (threadIdx.x == 0) *out_scalar = (red[0] + g_info) * wr_p[0];
}

// ---------------------------------------------------------------------------
// Y[r,c] = sum_k out[r,k]*W_fc[k,c] + b_fc[c] + X_B[r,c]
// (round-4 scalar-FFMA form: known-good)
// ---------------------------------------------------------------------------
__global__ void y_kernel(const float* __restrict__ X,
                         const float* __restrict__ W_fc,
                         const float* __restrict__ b_fc,
                         float* __restrict__ Y) {
    __shared__ float Xs[16][CC];
    const int row0 = blockIdx.x * 16;
    for (int i = threadIdx.x; i < 16 * CC; i += 256) {
        const int r = i >> 7, c = i & 127;
        Xs[r][c] = g_out[(size_t)(row0 + r) * CC + c];
    }
    __syncthreads();

    const int cg = threadIdx.x & 31;
    const int rg = threadIdx.x >> 5;
    const float4* W4 = (const float4*)W_fc;

    float4 acc0 = make_float4(0.f, 0.f, 0.f, 0.f);
    float4 acc1 = make_float4(0.f, 0.f, 0.f, 0.f);

    #pragma unroll 4
    for (int k = 0; k < CC; k++) {
        const float4 wv = W4[k * 32 + cg];
        const float x0 = Xs[rg * 2 + 0][k];
        const float x1 = Xs[rg * 2 + 1][k];
        acc0.x = fmaf(x0, wv.x, acc0.x); acc0.y = fmaf(x0, wv.y, acc0.y);
        acc0.z = fmaf(x0, wv.z, acc0.z); acc0.w = fmaf(x0, wv.w, acc0.w);
        acc1.x = fmaf(x1, wv.x, acc1.x); acc1.y = fmaf(x1, wv.y, acc1.y);
        acc1.z = fmaf(x1, wv.z, acc1.z); acc1.w = fmaf(x1, wv.w, acc1.w);
    }

    const float4 bf = ((const float4*)b_fc)[cg];
    {
        const int row = row0 + rg * 2;
        const float4 xb = ((const float4*)(X + (size_t)row * CC))[cg];
        ((float4*)(Y + (size_t)row * CC))[cg] =
            make_float4(acc0.x + bf.x + xb.x, acc0.y + bf.y + xb.y,
                        acc0.z + bf.z + xb.z, acc0.w + bf.w + xb.w);
    }
    {
        const int row = row0 + rg * 2 + 1;
        const float4 xb = ((const float4*)(X + (size_t)row * CC))[cg];
        ((float4*)(Y + (size_t)row * CC))[cg] =
            make_float4(acc1.x + bf.x + xb.x, acc1.y + bf.y + xb.y,
                        acc1.z + bf.z + xb.z, acc1.w + bf.w + xb.w);
    }
}

// ---------------------------------------------------------------------------
extern "C" void kernel_launch(void* const* d_in, const int* in_sizes, int n_in,
                              void* d_out, int out_size) {
    const float* X_B      = (const float*)d_in[0];
    const int*   esrc_bb  = (const int*)  d_in[1];
    const int*   edst_bb  = (const int*)  d_in[2];
    const float* ew_bb    = (const float*)d_in[3];
    const int*   esrc_bm  = (const int*)  d_in[4];
    const int*   edst_bm  = (const int*)  d_in[5];
    const float* ew_bm    = (const float*)d_in[6];
    const int*   c_idx    = (const int*)  d_in[7];
    const float* wr       = (const float*)d_in[8];
    const float* codebook = (const float*)d_in[9];
    const float* vq_grad  = (const float*)d_in[10];
    const float* W_conv   = (const float*)d_in[11];
    const float* b_conv   = (const float*)d_in[12];
    const float* W_fc     = (const float*)d_in[13];
    const float* b_fc     = (const float*)d_in[14];
    float* out = (float*)d_out;

    const int Ebb  = in_sizes[1];
    const int Ebm  = in_sizes[4];
    const int Etot = Ebb + Ebm;

    prep_kernel<<<(BN + 255) / 256, 256>>>(vq_grad);
    fill_dst_kernel<<<(Etot + 255) / 256, 256>>>(esrc_bb, edst_bb, ew_bb,
                                                 esrc_bm, edst_bm, ew_bm,
                                                 c_idx, Ebb, Etot);
    vsum_kernel<<<(BN * 32 + 255) / 256, 256>>>();
    {
        const int warps = ((NODES + 31) / 32) * NBR;
        compute_h_kernel<<<(warps * 32 + 255) / 256, 256>>>(X_B, codebook, W_conv, wr);
    }
    gather_kernel<<<(BN * 32 + 255) / 256, 256>>>(b_conv);
    finalize_kernel<<<1, 256>>>(vq_grad, b_conv, wr, out + (out_size - 1));
    y_kernel<<<BN / 16, 256>>>(X_B, W_fc, b_fc, out);
}

// round 8
// speedup vs baseline: 1.0446x; 1.0247x over previous
#include <cuda_runtime.h>
#include <cuda_fp16.h>
#include <cstdint>

#define BN     50000
#define NBR    4
#define DD     32
#define CC     128          // NBR*DD
#define MM     256
#define NODES  (BN + MM)    // 50256
#define CAPR   128          // per-batch-row bucket capacity (mean ~40)

// scratch (static device globals — no allocation)
__device__ __half g_h16[(size_t)NODES * CC];   // 12.9MB (Y path only)
__device__ float  g_out[(size_t)BN * CC];
__device__ int    g_cnt[BN];
__device__ int2   g_ent[(size_t)BN * CAPR];    // (src_row, w_bits) per batch-dst
__device__ float  g_vq32[MM * CC];             // vq_grad re-laid [m][b*32+e], 128KB
__device__ float  g_vsum[(size_t)BN * CC];     // per-row sum w*vq (fp32)
__device__ float  g_info;

// ---------------------------------------------------------------------------
// prep: zero counters/info + relayout vq_grad [b][m][e] -> [m][b*32+e]
// ---------------------------------------------------------------------------
__global__ void prep_kernel(const float* __restrict__ vq_grad) {
    const int idx = blockIdx.x * blockDim.x + threadIdx.x;
    if (idx < NBR * MM * DD) {
        const int b = idx >> 13;
        const int m = (idx >> 5) & (MM - 1);
        const int e = idx & 31;
        g_vq32[m * CC + b * DD + e] = vq_grad[idx];
    }
    if (idx < BN) g_cnt[idx] = 0;
    if (idx == 0) g_info = 0.0f;
}

// ---------------------------------------------------------------------------
// Bucket all edges by destination batch row (1 edge per thread).
// ---------------------------------------------------------------------------
__global__ void fill_dst_kernel(const int* __restrict__ sbb, const int* __restrict__ dbb,
                                const float* __restrict__ wbb,
                                const int* __restrict__ sbm, const int* __restrict__ dbm,
                                const float* __restrict__ wbm,
                                const int* __restrict__ cidx, int Ebb, int Etot) {
    const int i = blockIdx.x * blockDim.x + threadIdx.x;
    if (i >= Etot) return;
    int r, s; float w;
    if (i < Ebb) { r = dbb[i]; s = sbb[i]; w = wbb[i]; }
    else { const int j = i - Ebb; r = dbm[j]; s = BN + cidx[sbm[j]]; w = wbm[j]; }
    const int pos = atomicAdd(&g_cnt[r], 1);
    if (pos < CAPR)
        g_ent[(size_t)r * CAPR + pos] = make_int2(s, __float_as_int(w));
}

// ---------------------------------------------------------------------------
// vsum[r] = sum over bucket entries with src >= BN of w * vq32[src-BN].
// Entries are warp-uniform -> branch is divergence-free and skips ~60% of
// vq loads. 4-wide entry lookahead keeps L2 entry loads overlapped.
// ---------------------------------------------------------------------------
__device__ __forceinline__ void vs_proc(float4& vs, int2 E, int lane) {
    if (E.x >= BN) {                     // warp-uniform branch
        const float w = __int_as_float(E.y);
        const float4 qv = ((const float4*)(g_vq32 + (size_t)(E.x - BN) * CC))[lane];
        vs.x = fmaf(w, qv.x, vs.x); vs.y = fmaf(w, qv.y, vs.y);
        vs.z = fmaf(w, qv.z, vs.z); vs.w = fmaf(w, qv.w, vs.w);
    }
}

__global__ void vsum_kernel() {
    const int gw   = (blockIdx.x * blockDim.x + threadIdx.x) >> 5;
    const int lane = threadIdx.x & 31;
    if (gw >= BN) return;
    int n = g_cnt[gw]; if (n > CAPR) n = CAPR;

    const int2* ep = g_ent + (size_t)gw * CAPR;
    const int2 Z = make_int2(0, 0);     // src 0 < BN -> skipped
    float4 vs = make_float4(0.f, 0.f, 0.f, 0.f);

    int2 c0 = (0 < n) ? ep[0] : Z;
    int2 c1 = (1 < n) ? ep[1] : Z;
    int2 c2 = (2 < n) ? ep[2] : Z;
    int2 c3 = (3 < n) ? ep[3] : Z;
    for (int e = 0; e < n; e += 4) {
        const int2 n0 = (e + 4 < n) ? ep[e + 4] : Z;
        const int2 n1 = (e + 5 < n) ? ep[e + 5] : Z;
        const int2 n2 = (e + 6 < n) ? ep[e + 6] : Z;
        const int2 n3 = (e + 7 < n) ? ep[e + 7] : Z;
        vs_proc(vs, c0, lane); vs_proc(vs, c1, lane);
        vs_proc(vs, c2, lane); vs_proc(vs, c3, lane);
        c0 = n0; c1 = n1; c2 = n2; c3 = n3;
    }
    ((float4*)(g_vsum + (size_t)gw * CC))[lane] = vs;
}

// ---------------------------------------------------------------------------
// compute_h: ONE WARP PER ROW via width-8 shuffles.
// Lane owns output cols [4*lane .. 4*lane+3] (branch b = lane>>3).
// x row loaded as float4/lane (coalesced 512B); x_b[d] (d = 4i+j) comes from
// lane (l&~7)+i component j via __shfl_sync width 8.
// h written fp16 (uint2/lane, 256B/row); exact fp32 info dot vs g_vsum,
// block-reduced -> 1 atomic per block.
// ---------------------------------------------------------------------------
__global__ void compute_h_kernel(const float* __restrict__ X,
                                 const float* __restrict__ codebook,
                                 const float* __restrict__ W_conv,
                                 const float* __restrict__ wr_p) {
    __shared__ float Ws[NBR * DD * DD];   // 16KB, [b][d][e]
    __shared__ float wred[8];
    for (int i = threadIdx.x; i < NBR * DD * DD; i += blockDim.x)
        Ws[i] = W_conv[i];
    __syncthreads();

    const int lane = threadIdx.x & 31;
    const int wid  = threadIdx.x >> 5;
    const int row  = blockIdx.x * 8 + wid;       // grid covers NODES exactly
    const int b    = lane >> 3;
    const int sub  = lane & 7;

    float4 x4;
    if (row < BN) {
        x4 = ((const float4*)(X + (size_t)row * CC))[lane];
    } else {
        const float wr = wr_p[0];
        const int m = row - BN;
        x4 = ((const float4*)(codebook + ((size_t)b * MM + m) * DD))[sub];
        x4.x *= wr; x4.y *= wr; x4.z *= wr; x4.w *= wr;
    }

    float4 acc = make_float4(0.f, 0.f, 0.f, 0.f);
    const float* wb = &Ws[b * (DD * DD) + sub * 4];

    #pragma unroll
    for (int i = 0; i < 8; i++) {
        float xs[4];
        xs[0] = __shfl_sync(0xFFFFFFFF, x4.x, i, 8);
        xs[1] = __shfl_sync(0xFFFFFFFF, x4.y, i, 8);
        xs[2] = __shfl_sync(0xFFFFFFFF, x4.z, i, 8);
        xs[3] = __shfl_sync(0xFFFFFFFF, x4.w, i, 8);
        #pragma unroll
        for (int j = 0; j < 4; j++) {
            const int d = 4 * i + j;
            const float4 wv = *(const float4*)(wb + d * DD);
            acc.x = fmaf(xs[j], wv.x, acc.x);
            acc.y = fmaf(xs[j], wv.y, acc.y);
            acc.z = fmaf(xs[j], wv.z, acc.z);
            acc.w = fmaf(xs[j], wv.w, acc.w);
        }
    }

    // info partial: exact fp32 dot with vsum[row] (batch rows only)
    float p = 0.0f;
    if (row < BN) {
        const float4 vs = ((const float4*)(g_vsum + (size_t)row * CC))[lane];
        p = acc.x * vs.x + acc.y * vs.y + acc.z * vs.z + acc.w * vs.w;
    }
    #pragma unroll
    for (int s = 16; s > 0; s >>= 1)
        p += __shfl_xor_sync(0xFFFFFFFF, p, s);
    if (lane == 0) wred[wid] = p;

    // store h row as fp16 (8B per lane, contiguous 256B per warp)
    __half2 h0 = __floats2half2_rn(acc.x, acc.y);
    __half2 h1 = __floats2half2_rn(acc.z, acc.w);
    uint2 pk;
    pk.x = *(unsigned*)&h0;
    pk.y = *(unsigned*)&h1;
    ((uint2*)(g_h16 + (size_t)row * CC))[lane] = pk;

    __syncthreads();
    if (threadIdx.x == 0) {
        float s = wred[0] + wred[1] + wred[2] + wred[3]
                + wred[4] + wred[5] + wred[6] + wred[7];
        if (s != 0.0f) atomicAdd(&g_info, s);
    }
}

// ---------------------------------------------------------------------------
// Gather: one warp per batch row. out[r] = b_conv + sum w * h16[src].
// ---------------------------------------------------------------------------
__device__ __forceinline__ void fma_h16(float4& acc, int2 ent, uint2 hv) {
    const float w = __int_as_float(ent.y);
    const float2 f0 = __half22float2(*(const __half2*)&hv.x);
    const float2 f1 = __half22float2(*(const __half2*)&hv.y);
    acc.x = fmaf(w, f0.x, acc.x); acc.y = fmaf(w, f0.y, acc.y);
    acc.z = fmaf(w, f1.x, acc.z); acc.w = fmaf(w, f1.y, acc.w);
}

__global__ void gather_kernel(const float* __restrict__ b_conv) {
    const int gw   = (blockIdx.x * blockDim.x + threadIdx.x) >> 5;
    const int lane = threadIdx.x & 31;
    if (gw >= BN) return;
    int n = g_cnt[gw]; if (n > CAPR) n = CAPR;

    float4 acc = ((const float4*)b_conv)[lane];
    const int2* ep = g_ent + (size_t)gw * CAPR;
    const int2 Z = make_int2(0, 0);   // w bits == 0.0f

    int2 eA = (n > 0) ? ep[0] : Z;
    int2 eB = (n > 1) ? ep[1] : Z;
    uint2 hA = ((const uint2*)(g_h16 + (size_t)eA.x * CC))[lane];
    uint2 hB = ((const uint2*)(g_h16 + (size_t)eB.x * CC))[lane];

    for (int e = 0; e < n; e += 2) {
        const int2 nA = (e + 2 < n) ? ep[e + 2] : Z;
        const int2 nB = (e + 3 < n) ? ep[e + 3] : Z;
        const uint2 nhA = ((const uint2*)(g_h16 + (size_t)nA.x * CC))[lane];
        const uint2 nhB = ((const uint2*)(g_h16 + (size_t)nB.x * CC))[lane];
        fma_h16(acc, eA, hA);
        fma_h16(acc, eB, hB);
        eA = nA; hA = nhA; eB = nB; hB = nhB;
    }
    ((float4*)(g_out + (size_t)gw * CC))[lane] = acc;
}

// ---------------------------------------------------------------------------
// finalize: out_scalar = (g_info + sum b_conv[col]*vq[b,m,e]) * wr
// ---------------------------------------------------------------------------
__global__ void finalize_kernel(const float* __restrict__ vq_grad,
                                const float* __restrict__ b_conv,
                                const float* __restrict__ wr_p,
                                float* __restrict__ out_scalar) {
    __shared__ float red[256];
    float s = 0.0f;
    for (int idx = threadIdx.x; idx < NBR * MM * DD; idx += 256) {
        const int b = idx >> 13;
        const int e = idx & 31;
        s += b_conv[b * DD + e] * vq_grad[idx];
    }
    red[threadIdx.x] = s;
    __syncthreads();
    for (int st = 128; st > 0; st >>= 1) {
        if (threadIdx.x < st) red[threadIdx.x] += red[threadIdx.x + st];
        __syncthreads();
    }
    if (threadIdx.x == 0) *out_scalar = (red[0] + g_info) * wr_p[0];
}

// ---------------------------------------------------------------------------
// Y[r,c] = sum_k out[r,k]*W_fc[k,c] + b_fc[c] + X_B[r,c]
// (scalar-FFMA form: known-good)
// ---------------------------------------------------------------------------
__global__ void y_kernel(const float* __restrict__ X,
                         const float* __restrict__ W_fc,
                         const float* __restrict__ b_fc,
                         float* __restrict__ Y) {
    __shared__ float Xs[16][CC];
    const int row0 = blockIdx.x * 16;
    for (int i = threadIdx.x; i < 16 * CC; i += 256) {
        const int r = i >> 7, c = i & 127;
        Xs[r][c] = g_out[(size_t)(row0 + r) * CC + c];
    }
    __syncthreads();

    const int cg = threadIdx.x & 31;
    const int rg = threadIdx.x >> 5;
    const float4* W4 = (const float4*)W_fc;

    float4 acc0 = make_float4(0.f, 0.f, 0.f, 0.f);
    float4 acc1 = make_float4(0.f, 0.f, 0.f, 0.f);

    #pragma unroll 4
    for (int k = 0; k < CC; k++) {
        const float4 wv = W4[k * 32 + cg];
        const float x0 = Xs[rg * 2 + 0][k];
        const float x1 = Xs[rg * 2 + 1][k];
        acc0.x = fmaf(x0, wv.x, acc0.x); acc0.y = fmaf(x0, wv.y, acc0.y);
        acc0.z = fmaf(x0, wv.z, acc0.z); acc0.w = fmaf(x0, wv.w, acc0.w);
        acc1.x = fmaf(x1, wv.x, acc1.x); acc1.y = fmaf(x1, wv.y, acc1.y);
        acc1.z = fmaf(x1, wv.z, acc1.z); acc1.w = fmaf(x1, wv.w, acc1.w);
    }

    const float4 bf = ((const float4*)b_fc)[cg];
    {
        const int row = row0 + rg * 2;
        const float4 xb = ((const float4*)(X + (size_t)row * CC))[cg];
        ((float4*)(Y + (size_t)row * CC))[cg] =
            make_float4(acc0.x + bf.x + xb.x, acc0.y + bf.y + xb.y,
                        acc0.z + bf.z + xb.z, acc0.w + bf.w + xb.w);
    }
    {
        const int row = row0 + rg * 2 + 1;
        const float4 xb = ((const float4*)(X + (size_t)row * CC))[cg];
        ((float4*)(Y + (size_t)row * CC))[cg] =
            make_float4(acc1.x + bf.x + xb.x, acc1.y + bf.y + xb.y,
                        acc1.z + bf.z + xb.z, acc1.w + bf.w + xb.w);
    }
}

// ---------------------------------------------------------------------------
extern "C" void kernel_launch(void* const* d_in, const int* in_sizes, int n_in,
                              void* d_out, int out_size) {
    const float* X_B      = (const float*)d_in[0];
    const int*   esrc_bb  = (const int*)  d_in[1];
    const int*   edst_bb  = (const int*)  d_in[2];
    const float* ew_bb    = (const float*)d_in[3];
    const int*   esrc_bm  = (const int*)  d_in[4];
    const int*   edst_bm  = (const int*)  d_in[5];
    const float* ew_bm    = (const float*)d_in[6];
    const int*   c_idx    = (const int*)  d_in[7];
    const float* wr       = (const float*)d_in[8];
    const float* codebook = (const float*)d_in[9];
    const float* vq_grad  = (const float*)d_in[10];
    const float* W_conv   = (const float*)d_in[11];
    const float* b_conv   = (const float*)d_in[12];
    const float* W_fc     = (const float*)d_in[13];
    const float* b_fc     = (const float*)d_in[14];
    float* out = (float*)d_out;

    const int Ebb  = in_sizes[1];
    const int Ebm  = in_sizes[4];
    const int Etot = Ebb + Ebm;

    prep_kernel<<<(BN + 255) / 256, 256>>>(vq_grad);
    fill_dst_kernel<<<(Etot + 255) / 256, 256>>>(esrc_bb, edst_bb, ew_bb,
                                                 esrc_bm, edst_bm, ew_bm,
                                                 c_idx, Ebb, Etot);
    vsum_kernel<<<(BN * 32 + 255) / 256, 256>>>();
    compute_h_kernel<<<NODES / 8, 256>>>(X_B, codebook, W_conv, wr);  // 50256/8 = 6282
    gather_kernel<<<(BN * 32 + 255) / 256, 256>>>(b_conv);
    finalize_kernel<<<1, 256>>>(vq_grad, b_conv, wr, out + (out_size - 1));
    y_kernel<<<BN / 16, 256>>>(X_B, W_fc, b_fc, out);
}

// round 9
// speedup vs baseline: 1.0928x; 1.0461x over previous
#include <cuda_runtime.h>
#include <cuda_fp16.h>
#include <cstdint>

#define BN     50000
#define NBR    4
#define DD     32
#define CC     128          // NBR*DD
#define MM     256
#define NODES  (BN + MM)    // 50256
#define CAPR   128          // per-batch-row bucket capacity (mean ~40)
#define HROWS  64           // rows per compute_h block
#define XPAD   132          // padded row stride (floats) to avoid bank conflicts

// scratch (static device globals — no allocation)
__device__ __half g_h16[(size_t)NODES * CC];   // 12.9MB (Y path only)
__device__ float  g_out[(size_t)BN * CC];
__device__ int    g_cnt[BN];
__device__ int2   g_ent[(size_t)BN * CAPR];    // (src_row, w_bits) per batch-dst
__device__ float  g_vq32[MM * CC];             // vq_grad re-laid [m][b*32+e], 128KB
__device__ float  g_vsum[(size_t)BN * CC];     // per-row sum w*vq (fp32)
__device__ float  g_info;

// ---------------------------------------------------------------------------
// prep: zero counters/info + relayout vq_grad [b][m][e] -> [m][b*32+e]
// ---------------------------------------------------------------------------
__global__ void prep_kernel(const float* __restrict__ vq_grad) {
    const int idx = blockIdx.x * blockDim.x + threadIdx.x;
    if (idx < NBR * MM * DD) {
        const int b = idx >> 13;
        const int m = (idx >> 5) & (MM - 1);
        const int e = idx & 31;
        g_vq32[m * CC + b * DD + e] = vq_grad[idx];
    }
    if (idx < BN) g_cnt[idx] = 0;
    if (idx == 0) g_info = 0.0f;
}

// ---------------------------------------------------------------------------
// Bucket all edges by destination batch row (1 edge per thread).
// ---------------------------------------------------------------------------
__global__ void fill_dst_kernel(const int* __restrict__ sbb, const int* __restrict__ dbb,
                                const float* __restrict__ wbb,
                                const int* __restrict__ sbm, const int* __restrict__ dbm,
                                const float* __restrict__ wbm,
                                const int* __restrict__ cidx, int Ebb, int Etot) {
    const int i = blockIdx.x * blockDim.x + threadIdx.x;
    if (i >= Etot) return;
    int r, s; float w;
    if (i < Ebb) { r = dbb[i]; s = sbb[i]; w = wbb[i]; }
    else { const int j = i - Ebb; r = dbm[j]; s = BN + cidx[sbm[j]]; w = wbm[j]; }
    const int pos = atomicAdd(&g_cnt[r], 1);
    if (pos < CAPR)
        g_ent[(size_t)r * CAPR + pos] = make_int2(s, __float_as_int(w));
}

// ---------------------------------------------------------------------------
// vsum[r] = sum over bucket entries with src >= BN of w * vq32[src-BN].
// Warp-uniform branch skips bb entries; 4-wide entry lookahead.
// ---------------------------------------------------------------------------
__device__ __forceinline__ void vs_proc(float4& vs, int2 E, int lane) {
    if (E.x >= BN) {                     // warp-uniform branch
        const float w = __int_as_float(E.y);
        const float4 qv = ((const float4*)(g_vq32 + (size_t)(E.x - BN) * CC))[lane];
        vs.x = fmaf(w, qv.x, vs.x); vs.y = fmaf(w, qv.y, vs.y);
        vs.z = fmaf(w, qv.z, vs.z); vs.w = fmaf(w, qv.w, vs.w);
    }
}

__global__ void vsum_kernel() {
    const int gw   = (blockIdx.x * blockDim.x + threadIdx.x) >> 5;
    const int lane = threadIdx.x & 31;
    if (gw >= BN) return;
    int n = g_cnt[gw]; if (n > CAPR) n = CAPR;

    const int2* ep = g_ent + (size_t)gw * CAPR;
    const int2 Z = make_int2(0, 0);     // src 0 < BN -> skipped
    float4 vs = make_float4(0.f, 0.f, 0.f, 0.f);

    int2 c0 = (0 < n) ? ep[0] : Z;
    int2 c1 = (1 < n) ? ep[1] : Z;
    int2 c2 = (2 < n) ? ep[2] : Z;
    int2 c3 = (3 < n) ? ep[3] : Z;
    for (int e = 0; e < n; e += 4) {
        const int2 n0 = (e + 4 < n) ? ep[e + 4] : Z;
        const int2 n1 = (e + 5 < n) ? ep[e + 5] : Z;
        const int2 n2 = (e + 6 < n) ? ep[e + 6] : Z;
        const int2 n3 = (e + 7 < n) ? ep[e + 7] : Z;
        vs_proc(vs, c0, lane); vs_proc(vs, c1, lane);
        vs_proc(vs, c2, lane); vs_proc(vs, c3, lane);
        c0 = n0; c1 = n1; c2 = n2; c3 = n3;
    }
    ((float4*)(g_vsum + (size_t)gw * CC))[lane] = vs;
}

// ---------------------------------------------------------------------------
// compute_h v3: register-tiled GEMM.
// Block stages 64 rows of X_in into padded shared. Warp = 32 rows x 1 branch
// (wid>>2 selects row-half, wid&3 selects branch). Thread = 4 rows x 8 cols:
//   lane = rg*4+cg, rows = rg + 8*rr, cols = b*32 + cg*8 .. +7.
// Per d: 2 LDS.128 of W (reused over 4 rows) + 4 bcast LDS of x + 32 FMA.
// h stored fp16 (uint4 = 8 cols per row); exact fp32 info dot vs g_vsum.
// ---------------------------------------------------------------------------
__global__ void compute_h_kernel(const float* __restrict__ X,
                                 const float* __restrict__ codebook,
                                 const float* __restrict__ W_conv,
                                 const float* __restrict__ wr_p) {
    __shared__ float Ws[NBR * DD * DD];   // 16KB, [b][d][e]
    __shared__ float Xs[HROWS][XPAD];     // 33KB padded
    __shared__ float wred[8];

    for (int i = threadIdx.x; i < NBR * DD * DD; i += blockDim.x)
        Ws[i] = W_conv[i];

    const int row0 = blockIdx.x * HROWS;
    const float wr = wr_p[0];

    // stage 64 rows of X_in (X for batch rows, codebook*wr for codeword rows)
    for (int i = threadIdx.x; i < HROWS * 32; i += 256) {
        const int r  = i >> 5;
        const int c4 = i & 31;            // float4 column index (0..31)
        const int row = row0 + r;
        float4 v = make_float4(0.f, 0.f, 0.f, 0.f);
        if (row < BN) {
            v = ((const float4*)X)[(size_t)row * 32 + c4];
        } else if (row < NODES) {
            const int b = c4 >> 3, sub = c4 & 7, m = row - BN;
            v = ((const float4*)codebook)[((size_t)b * MM + m) * 8 + sub];
            v.x *= wr; v.y *= wr; v.z *= wr; v.w *= wr;
        }
        *(float4*)&Xs[r][c4 * 4] = v;
    }
    __syncthreads();

    const int wid  = threadIdx.x >> 5;
    const int lane = threadIdx.x & 31;
    const int rgrp = wid >> 2;            // 0/1: which 32-row half
    const int b    = wid & 3;             // branch
    const int rg   = lane >> 2;           // 0..7
    const int cg   = lane & 3;            // 0..3 -> cols cg*8..cg*8+7

    float acc[4][8];
    #pragma unroll
    for (int rr = 0; rr < 4; rr++)
        #pragma unroll
        for (int c = 0; c < 8; c++) acc[rr][c] = 0.0f;

    const float* wbp = &Ws[b * (DD * DD) + cg * 8];
    const int lrow0 = rgrp * 32 + rg;

    #pragma unroll
    for (int d = 0; d < DD; d++) {
        const float4 wv0 = *(const float4*)(wbp + d * DD);
        const float4 wv1 = *(const float4*)(wbp + d * DD + 4);
        #pragma unroll
        for (int rr = 0; rr < 4; rr++) {
            const float xv = Xs[lrow0 + 8 * rr][b * DD + d];
            acc[rr][0] = fmaf(xv, wv0.x, acc[rr][0]);
            acc[rr][1] = fmaf(xv, wv0.y, acc[rr][1]);
            acc[rr][2] = fmaf(xv, wv0.z, acc[rr][2]);
            acc[rr][3] = fmaf(xv, wv0.w, acc[rr][3]);
            acc[rr][4] = fmaf(xv, wv1.x, acc[rr][4]);
            acc[rr][5] = fmaf(xv, wv1.y, acc[rr][5]);
            acc[rr][6] = fmaf(xv, wv1.z, acc[rr][6]);
            acc[rr][7] = fmaf(xv, wv1.w, acc[rr][7]);
        }
    }

    // info partials + fp16 stores
    float p = 0.0f;
    #pragma unroll
    for (int rr = 0; rr < 4; rr++) {
        const int row = row0 + lrow0 + 8 * rr;
        if (row < BN) {
            const float4* vp = (const float4*)(g_vsum + (size_t)row * CC + b * DD + cg * 8);
            const float4 v0 = vp[0];
            const float4 v1 = vp[1];
            p = fmaf(acc[rr][0], v0.x, p); p = fmaf(acc[rr][1], v0.y, p);
            p = fmaf(acc[rr][2], v0.z, p); p = fmaf(acc[rr][3], v0.w, p);
            p = fmaf(acc[rr][4], v1.x, p); p = fmaf(acc[rr][5], v1.y, p);
            p = fmaf(acc[rr][6], v1.z, p); p = fmaf(acc[rr][7], v1.w, p);
        }
        if (row < NODES) {
            __half2 h0 = __floats2half2_rn(acc[rr][0], acc[rr][1]);
            __half2 h1 = __floats2half2_rn(acc[rr][2], acc[rr][3]);
            __half2 h2 = __floats2half2_rn(acc[rr][4], acc[rr][5]);
            __half2 h3 = __floats2half2_rn(acc[rr][6], acc[rr][7]);
            uint4 pk;
            pk.x = *(unsigned*)&h0; pk.y = *(unsigned*)&h1;
            pk.z = *(unsigned*)&h2; pk.w = *(unsigned*)&h3;
            *(uint4*)(g_h16 + (size_t)row * CC + b * DD + cg * 8) = pk;
        }
    }

    #pragma unroll
    for (int s = 16; s > 0; s >>= 1)
        p += __shfl_xor_sync(0xFFFFFFFF, p, s);
    if (lane == 0) wred[wid] = p;
    __syncthreads();
    if (threadIdx.x == 0) {
        float s = wred[0] + wred[1] + wred[2] + wred[3]
                + wred[4] + wred[5] + wred[6] + wred[7];
        if (s != 0.0f) atomicAdd(&g_info, s);
    }
}

// ---------------------------------------------------------------------------
// Gather: one warp per batch row. out[r] = b_conv + sum w * h16[src].
// ---------------------------------------------------------------------------
__device__ __forceinline__ void fma_h16(float4& acc, int2 ent, uint2 hv) {
    const float w = __int_as_float(ent.y);
    const float2 f0 = __half22float2(*(const __half2*)&hv.x);
    const float2 f1 = __half22float2(*(const __half2*)&hv.y);
    acc.x = fmaf(w, f0.x, acc.x); acc.y = fmaf(w, f0.y, acc.y);
    acc.z = fmaf(w, f1.x, acc.z); acc.w = fmaf(w, f1.y, acc.w);
}

__global__ void gather_kernel(const float* __restrict__ b_conv) {
    const int gw   = (blockIdx.x * blockDim.x + threadIdx.x) >> 5;
    const int lane = threadIdx.x & 31;
    if (gw >= BN) return;
    int n = g_cnt[gw]; if (n > CAPR) n = CAPR;

    float4 acc = ((const float4*)b_conv)[lane];
    const int2* ep = g_ent + (size_t)gw * CAPR;
    const int2 Z = make_int2(0, 0);   // w bits == 0.0f

    int2 eA = (n > 0) ? ep[0] : Z;
    int2 eB = (n > 1) ? ep[1] : Z;
    uint2 hA = ((const uint2*)(g_h16 + (size_t)eA.x * CC))[lane];
    uint2 hB = ((const uint2*)(g_h16 + (size_t)eB.x * CC))[lane];

    for (int e = 0; e < n; e += 2) {
        const int2 nA = (e + 2 < n) ? ep[e + 2] : Z;
        const int2 nB = (e + 3 < n) ? ep[e + 3] : Z;
        const uint2 nhA = ((const uint2*)(g_h16 + (size_t)nA.x * CC))[lane];
        const uint2 nhB = ((const uint2*)(g_h16 + (size_t)nB.x * CC))[lane];
        fma_h16(acc, eA, hA);
        fma_h16(acc, eB, hB);
        eA = nA; hA = nhA; eB = nB; hB = nhB;
    }
    ((float4*)(g_out + (size_t)gw * CC))[lane] = acc;
}

// ---------------------------------------------------------------------------
// finalize: out_scalar = (g_info + sum b_conv[col]*vq[b,m,e]) * wr
// ---------------------------------------------------------------------------
__global__ void finalize_kernel(const float* __restrict__ vq_grad,
                                const float* __restrict__ b_conv,
                                const float* __restrict__ wr_p,
                                float* __restrict__ out_scalar) {
    __shared__ float red[256];
    float s = 0.0f;
    for (int idx = threadIdx.x; idx < NBR * MM * DD; idx += 256) {
        const int b = idx >> 13;
        const int e = idx & 31;
        s += b_conv[b * DD + e] * vq_grad[idx];
    }
    red[threadIdx.x] = s;
    __syncthreads();
    for (int st = 128; st > 0; st >>= 1) {
        if (threadIdx.x < st) red[threadIdx.x] += red[threadIdx.x + st];
        __syncthreads();
    }
    if (threadIdx.x == 0) *out_scalar = (red[0] + g_info) * wr_p[0];
}

// ---------------------------------------------------------------------------
// Y[r,c] = sum_k out[r,k]*W_fc[k,c] + b_fc[c] + X_B[r,c]
// (scalar-FFMA form: known-good)
// ---------------------------------------------------------------------------
__global__ void y_kernel(const float* __restrict__ X,
                         const float* __restrict__ W_fc,
                         const float* __restrict__ b_fc,
                         float* __restrict__ Y) {
    __shared__ float Xs[16][CC];
    const int row0 = blockIdx.x * 16;
    for (int i = threadIdx.x; i < 16 * CC; i += 256) {
        const int r = i >> 7, c = i & 127;
        Xs[r][c] = g_out[(size_t)(row0 + r) * CC + c];
    }
    __syncthreads();

    const int cg = threadIdx.x & 31;
    const int rg = threadIdx.x >> 5;
    const float4* W4 = (const float4*)W_fc;

    float4 acc0 = make_float4(0.f, 0.f, 0.f, 0.f);
    float4 acc1 = make_float4(0.f, 0.f, 0.f, 0.f);

    #pragma unroll 4
    for (int k = 0; k < CC; k++) {
        const float4 wv = W4[k * 32 + cg];
        const float x0 = Xs[rg * 2 + 0][k];
        const float x1 = Xs[rg * 2 + 1][k];
        acc0.x = fmaf(x0, wv.x, acc0.x); acc0.y = fmaf(x0, wv.y, acc0.y);
        acc0.z = fmaf(x0, wv.z, acc0.z); acc0.w = fmaf(x0, wv.w, acc0.w);
        acc1.x = fmaf(x1, wv.x, acc1.x); acc1.y = fmaf(x1, wv.y, acc1.y);
        acc1.z = fmaf(x1, wv.z, acc1.z); acc1.w = fmaf(x1, wv.w, acc1.w);
    }

    const float4 bf = ((const float4*)b_fc)[cg];
    {
        const int row = row0 + rg * 2;
        const float4 xb = ((const float4*)(X + (size_t)row * CC))[cg];
        ((float4*)(Y + (size_t)row * CC))[cg] =
            make_float4(acc0.x + bf.x + xb.x, acc0.y + bf.y + xb.y,
                        acc0.z + bf.z + xb.z, acc0.w + bf.w + xb.w);
    }
    {
        const int row = row0 + rg * 2 + 1;
        const float4 xb = ((const float4*)(X + (size_t)row * CC))[cg];
        ((float4*)(Y + (size_t)row * CC))[cg] =
            make_float4(acc1.x + bf.x + xb.x, acc1.y + bf.y + xb.y,
                        acc1.z + bf.z + xb.z, acc1.w + bf.w + xb.w);
    }
}

// ---------------------------------------------------------------------------
extern "C" void kernel_launch(void* const* d_in, const int* in_sizes, int n_in,
                              void* d_out, int out_size) {
    const float* X_B      = (const float*)d_in[0];
    const int*   esrc_bb  = (const int*)  d_in[1];
    const int*   edst_bb  = (const int*)  d_in[2];
    const float* ew_bb    = (const float*)d_in[3];
    const int*   esrc_bm  = (const int*)  d_in[4];
    const int*   edst_bm  = (const int*)  d_in[5];
    const float* ew_bm    = (const float*)d_in[6];
    const int*   c_idx    = (const int*)  d_in[7];
    const float* wr       = (const float*)d_in[8];
    const float* codebook = (const float*)d_in[9];
    const float* vq_grad  = (const float*)d_in[10];
    const float* W_conv   = (const float*)d_in[11];
    const float* b_conv   = (const float*)d_in[12];
    const float* W_fc     = (const float*)d_in[13];
    const float* b_fc     = (const float*)d_in[14];
    float* out = (float*)d_out;

    const int Ebb  = in_sizes[1];
    const int Ebm  = in_sizes[4];
    const int Etot = Ebb + Ebm;

    prep_kernel<<<(BN + 255) / 256, 256>>>(vq_grad);
    fill_dst_kernel<<<(Etot + 255) / 256, 256>>>(esrc_bb, edst_bb, ew_bb,
                                                 esrc_bm, edst_bm, ew_bm,
                                                 c_idx, Ebb, Etot);
    vsum_kernel<<<(BN * 32 + 255) / 256, 256>>>();
    compute_h_kernel<<<(NODES + HROWS - 1) / HROWS, 256>>>(X_B, codebook, W_conv, wr);
    gather_kernel<<<(BN * 32 + 255) / 256, 256>>>(b_conv);
    finalize_kernel<<<1, 256>>>(vq_grad, b_conv, wr, out + (out_size - 1));
    y_kernel<<<BN / 16, 256>>>(X_B, W_fc, b_fc, out);
}

// round 10
// speedup vs baseline: 1.2491x; 1.1430x over previous
#include <cuda_runtime.h>
#include <cuda_fp16.h>
#include <mma.h>
#include <cstdint>

using namespace nvcuda;

#define BN     50000
#define NBR    4
#define DD     32
#define CC     128          // NBR*DD
#define MM     256
#define NODES  (BN + MM)    // 50256
#define CAPR   128          // per-batch-row bucket capacity (mean ~40)
#define HROWS  64           // rows per compute_h block
#define XPAD   132          // padded row stride (floats)
#define YROWS  64           // rows per y block

// scratch (static device globals — no allocation)
__device__ __half g_h16[(size_t)NODES * CC];   // 12.9MB (Y path only)
__device__ __half g_out16[(size_t)BN * CC];    // gather result, fp16 (y input)
__device__ __half g_wfc16[CC * CC];            // W_fc in fp16
__device__ int    g_cnt[BN];
__device__ int2   g_ent[(size_t)BN * CAPR];    // (src_row, w_bits) per batch-dst
__device__ float  g_vq32[MM * CC];             // vq_grad re-laid [m][b*32+e], 128KB
__device__ float  g_vsum[(size_t)BN * CC];     // per-row sum w*vq (fp32)
__device__ float  g_info;

// ---------------------------------------------------------------------------
// prep: zero counters/info + relayout vq_grad + convert W_fc to fp16
// ---------------------------------------------------------------------------
__global__ void prep_kernel(const float* __restrict__ vq_grad,
                            const float* __restrict__ W_fc) {
    const int idx = blockIdx.x * blockDim.x + threadIdx.x;
    if (idx < NBR * MM * DD) {
        const int b = idx >> 13;
        const int m = (idx >> 5) & (MM - 1);
        const int e = idx & 31;
        g_vq32[m * CC + b * DD + e] = vq_grad[idx];
    }
    if (idx < CC * CC) g_wfc16[idx] = __float2half_rn(W_fc[idx]);
    if (idx < BN) g_cnt[idx] = 0;
    if (idx == 0) g_info = 0.0f;
}

// ---------------------------------------------------------------------------
// Bucket all edges by destination batch row (1 edge per thread).
// ---------------------------------------------------------------------------
__global__ void fill_dst_kernel(const int* __restrict__ sbb, const int* __restrict__ dbb,
                                const float* __restrict__ wbb,
                                const int* __restrict__ sbm, const int* __restrict__ dbm,
                                const float* __restrict__ wbm,
                                const int* __restrict__ cidx, int Ebb, int Etot) {
    const int i = blockIdx.x * blockDim.x + threadIdx.x;
    if (i >= Etot) return;
    int r, s; float w;
    if (i < Ebb) { r = dbb[i]; s = sbb[i]; w = wbb[i]; }
    else { const int j = i - Ebb; r = dbm[j]; s = BN + cidx[sbm[j]]; w = wbm[j]; }
    const int pos = atomicAdd(&g_cnt[r], 1);
    if (pos < CAPR)
        g_ent[(size_t)r * CAPR + pos] = make_int2(s, __float_as_int(w));
}

// ---------------------------------------------------------------------------
// vsum[r] = sum over bucket entries with src >= BN of w * vq32[src-BN].
// Warp-uniform branch skips bb entries; 4-wide entry lookahead.
// ---------------------------------------------------------------------------
__device__ __forceinline__ void vs_proc(float4& vs, int2 E, int lane) {
    if (E.x >= BN) {                     // warp-uniform branch
        const float w = __int_as_float(E.y);
        const float4 qv = ((const float4*)(g_vq32 + (size_t)(E.x - BN) * CC))[lane];
        vs.x = fmaf(w, qv.x, vs.x); vs.y = fmaf(w, qv.y, vs.y);
        vs.z = fmaf(w, qv.z, vs.z); vs.w = fmaf(w, qv.w, vs.w);
    }
}

__global__ void vsum_kernel() {
    const int gw   = (blockIdx.x * blockDim.x + threadIdx.x) >> 5;
    const int lane = threadIdx.x & 31;
    if (gw >= BN) return;
    int n = g_cnt[gw]; if (n > CAPR) n = CAPR;

    const int2* ep = g_ent + (size_t)gw * CAPR;
    const int2 Z = make_int2(0, 0);     // src 0 < BN -> skipped
    float4 vs = make_float4(0.f, 0.f, 0.f, 0.f);

    int2 c0 = (0 < n) ? ep[0] : Z;
    int2 c1 = (1 < n) ? ep[1] : Z;
    int2 c2 = (2 < n) ? ep[2] : Z;
    int2 c3 = (3 < n) ? ep[3] : Z;
    for (int e = 0; e < n; e += 4) {
        const int2 n0 = (e + 4 < n) ? ep[e + 4] : Z;
        const int2 n1 = (e + 5 < n) ? ep[e + 5] : Z;
        const int2 n2 = (e + 6 < n) ? ep[e + 6] : Z;
        const int2 n3 = (e + 7 < n) ? ep[e + 7] : Z;
        vs_proc(vs, c0, lane); vs_proc(vs, c1, lane);
        vs_proc(vs, c2, lane); vs_proc(vs, c3, lane);
        c0 = n0; c1 = n1; c2 = n2; c3 = n3;
    }
    ((float4*)(g_vsum + (size_t)gw * CC))[lane] = vs;
}

// ---------------------------------------------------------------------------
// compute_h v3: register-tiled GEMM (round-9, known-good).
// ---------------------------------------------------------------------------
__global__ void compute_h_kernel(const float* __restrict__ X,
                                 const float* __restrict__ codebook,
                                 const float* __restrict__ W_conv,
                                 const float* __restrict__ wr_p) {
    __shared__ float Ws[NBR * DD * DD];   // 16KB, [b][d][e]
    __shared__ float Xs[HROWS][XPAD];     // 33KB padded
    __shared__ float wred[8];

    for (int i = threadIdx.x; i < NBR * DD * DD; i += blockDim.x)
        Ws[i] = W_conv[i];

    const int row0 = blockIdx.x * HROWS;
    const float wr = wr_p[0];

    for (int i = threadIdx.x; i < HROWS * 32; i += 256) {
        const int r  = i >> 5;
        const int c4 = i & 31;
        const int row = row0 + r;
        float4 v = make_float4(0.f, 0.f, 0.f, 0.f);
        if (row < BN) {
            v = ((const float4*)X)[(size_t)row * 32 + c4];
        } else if (row < NODES) {
            const int b = c4 >> 3, sub = c4 & 7, m = row - BN;
            v = ((const float4*)codebook)[((size_t)b * MM + m) * 8 + sub];
            v.x *= wr; v.y *= wr; v.z *= wr; v.w *= wr;
        }
        *(float4*)&Xs[r][c4 * 4] = v;
    }
    __syncthreads();

    const int wid  = threadIdx.x >> 5;
    const int lane = threadIdx.x & 31;
    const int rgrp = wid >> 2;
    const int b    = wid & 3;
    const int rg   = lane >> 2;
    const int cg   = lane & 3;

    float acc[4][8];
    #pragma unroll
    for (int rr = 0; rr < 4; rr++)
        #pragma unroll
        for (int c = 0; c < 8; c++) acc[rr][c] = 0.0f;

    const float* wbp = &Ws[b * (DD * DD) + cg * 8];
    const int lrow0 = rgrp * 32 + rg;

    #pragma unroll
    for (int d = 0; d < DD; d++) {
        const float4 wv0 = *(const float4*)(wbp + d * DD);
        const float4 wv1 = *(const float4*)(wbp + d * DD + 4);
        #pragma unroll
        for (int rr = 0; rr < 4; rr++) {
            const float xv = Xs[lrow0 + 8 * rr][b * DD + d];
            acc[rr][0] = fmaf(xv, wv0.x, acc[rr][0]);
            acc[rr][1] = fmaf(xv, wv0.y, acc[rr][1]);
            acc[rr][2] = fmaf(xv, wv0.z, acc[rr][2]);
            acc[rr][3] = fmaf(xv, wv0.w, acc[rr][3]);
            acc[rr][4] = fmaf(xv, wv1.x, acc[rr][4]);
            acc[rr][5] = fmaf(xv, wv1.y, acc[rr][5]);
            acc[rr][6] = fmaf(xv, wv1.z, acc[rr][6]);
            acc[rr][7] = fmaf(xv, wv1.w, acc[rr][7]);
        }
    }

    float p = 0.0f;
    #pragma unroll
    for (int rr = 0; rr < 4; rr++) {
        const int row = row0 + lrow0 + 8 * rr;
        if (row < BN) {
            const float4* vp = (const float4*)(g_vsum + (size_t)row * CC + b * DD + cg * 8);
            const float4 v0 = vp[0];
            const float4 v1 = vp[1];
            p = fmaf(acc[rr][0], v0.x, p); p = fmaf(acc[rr][1], v0.y, p);
            p = fmaf(acc[rr][2], v0.z, p); p = fmaf(acc[rr][3], v0.w, p);
            p = fmaf(acc[rr][4], v1.x, p); p = fmaf(acc[rr][5], v1.y, p);
            p = fmaf(acc[rr][6], v1.z, p); p = fmaf(acc[rr][7], v1.w, p);
        }
        if (row < NODES) {
            __half2 h0 = __floats2half2_rn(acc[rr][0], acc[rr][1]);
            __half2 h1 = __floats2half2_rn(acc[rr][2], acc[rr][3]);
            __half2 h2 = __floats2half2_rn(acc[rr][4], acc[rr][5]);
            __half2 h3 = __floats2half2_rn(acc[rr][6], acc[rr][7]);
            uint4 pk;
            pk.x = *(unsigned*)&h0; pk.y = *(unsigned*)&h1;
            pk.z = *(unsigned*)&h2; pk.w = *(unsigned*)&h3;
            *(uint4*)(g_h16 + (size_t)row * CC + b * DD + cg * 8) = pk;
        }
    }

    #pragma unroll
    for (int s = 16; s > 0; s >>= 1)
        p += __shfl_xor_sync(0xFFFFFFFF, p, s);
    if (lane == 0) wred[wid] = p;
    __syncthreads();
    if (threadIdx.x == 0) {
        float s = wred[0] + wred[1] + wred[2] + wred[3]
                + wred[4] + wred[5] + wred[6] + wred[7];
        if (s != 0.0f) atomicAdd(&g_info, s);
    }
}

// ---------------------------------------------------------------------------
// Gather: one warp per batch row. out16[r] = fp16(b_conv + sum w * h16[src]).
// fp32 accumulation; fp16 store (y path uses tensor cores on out16).
// ---------------------------------------------------------------------------
__device__ __forceinline__ void fma_h16(float4& acc, int2 ent, uint2 hv) {
    const float w = __int_as_float(ent.y);
    const float2 f0 = __half22float2(*(const __half2*)&hv.x);
    const float2 f1 = __half22float2(*(const __half2*)&hv.y);
    acc.x = fmaf(w, f0.x, acc.x); acc.y = fmaf(w, f0.y, acc.y);
    acc.z = fmaf(w, f1.x, acc.z); acc.w = fmaf(w, f1.y, acc.w);
}

__global__ void gather_kernel(const float* __restrict__ b_conv) {
    const int gw   = (blockIdx.x * blockDim.x + threadIdx.x) >> 5;
    const int lane = threadIdx.x & 31;
    if (gw >= BN) return;
    int n = g_cnt[gw]; if (n > CAPR) n = CAPR;

    float4 acc = ((const float4*)b_conv)[lane];
    const int2* ep = g_ent + (size_t)gw * CAPR;
    const int2 Z = make_int2(0, 0);   // w bits == 0.0f

    int2 eA = (n > 0) ? ep[0] : Z;
    int2 eB = (n > 1) ? ep[1] : Z;
    uint2 hA = ((const uint2*)(g_h16 + (size_t)eA.x * CC))[lane];
    uint2 hB = ((const uint2*)(g_h16 + (size_t)eB.x * CC))[lane];

    for (int e = 0; e < n; e += 2) {
        const int2 nA = (e + 2 < n) ? ep[e + 2] : Z;
        const int2 nB = (e + 3 < n) ? ep[e + 3] : Z;
        const uint2 nhA = ((const uint2*)(g_h16 + (size_t)nA.x * CC))[lane];
        const uint2 nhB = ((const uint2*)(g_h16 + (size_t)nB.x * CC))[lane];
        fma_h16(acc, eA, hA);
        fma_h16(acc, eB, hB);
        eA = nA; hA = nhA; eB = nB; hB = nhB;
    }
    __half2 o0 = __floats2half2_rn(acc.x, acc.y);
    __half2 o1 = __floats2half2_rn(acc.z, acc.w);
    uint2 pk;
    pk.x = *(unsigned*)&o0;
    pk.y = *(unsigned*)&o1;
    ((uint2*)(g_out16 + (size_t)gw * CC))[lane] = pk;
}

// ---------------------------------------------------------------------------
// finalize: out_scalar = (g_info + sum b_conv[col]*vq[b,m,e]) * wr
// ---------------------------------------------------------------------------
__global__ void finalize_kernel(const float* __restrict__ vq_grad,
                                const float* __restrict__ b_conv,
                                const float* __restrict__ wr_p,
                                float* __restrict__ out_scalar) {
    __shared__ float red[256];
    float s = 0.0f;
    for (int idx = threadIdx.x; idx < NBR * MM * DD; idx += 256) {
        const int b = idx >> 13;
        const int e = idx & 31;
        s += b_conv[b * DD + e] * vq_grad[idx];
    }
    red[threadIdx.x] = s;
    __syncthreads();
    for (int st = 128; st > 0; st >>= 1) {
        if (threadIdx.x < st) red[threadIdx.x] += red[threadIdx.x + st];
        __syncthreads();
    }
    if (threadIdx.x == 0) *out_scalar = (red[0] + g_info) * wr_p[0];
}

// ---------------------------------------------------------------------------
// y_kernel (WMMA): Y[r,c] = (out16 @ W16)[r,c] + b_fc[c] + X_B[r,c]
// Block = 64 rows x 128 cols, 8 warps (256 thr).
// Warp w: row-tile rt = w>>1 (16 rows), col-half ch = w&1 (64 cols as 4 frags).
// smem: As 64x128 fp16 (16KB) + Bs 128x128 fp16 (32KB) = 48KB; epilogue
// reuses the same 48KB as a 64x128 fp32 buffer.
// ---------------------------------------------------------------------------
__global__ void y_kernel(const float* __restrict__ X,
                         const float* __restrict__ b_fc,
                         float* __restrict__ Y) {
    __shared__ __align__(16) char sraw[49152];
    __half* As = (__half*)sraw;                   // [64][128]
    __half* Bs = (__half*)(sraw + 16384);         // [128][128]
    float*  Ob = (float*)sraw;                    // [64][128] (after loop)

    const int row0 = blockIdx.x * YROWS;
    const int tid  = threadIdx.x;

    // stage A (64 x 128 halfs = 1024 uint4), zero-pad rows >= BN
    for (int i = tid; i < 1024; i += 256) {
        const int r = i >> 4, c16 = i & 15;
        const int row = row0 + r;
        uint4 v = make_uint4(0, 0, 0, 0);
        if (row < BN) v = ((const uint4*)(g_out16 + (size_t)row * CC))[c16];
        ((uint4*)As)[i] = v;
    }
    // stage B (128 x 128 halfs = 2048 uint4)
    for (int i = tid; i < 2048; i += 256)
        ((uint4*)Bs)[i] = ((const uint4*)g_wfc16)[i];
    __syncthreads();

    const int w  = tid >> 5;
    const int rt = w >> 1;          // 0..3
    const int ch = w & 1;           // 0/1

    wmma::fragment<wmma::accumulator, 16, 16, 16, float> accf[4];
    #pragma unroll
    for (int t = 0; t < 4; t++) wmma::fill_fragment(accf[t], 0.0f);

    #pragma unroll
    for (int k = 0; k < 8; k++) {
        wmma::fragment<wmma::matrix_a, 16, 16, 16, __half, wmma::row_major> af;
        wmma::load_matrix_sync(af, As + (rt * 16) * CC + k * 16, CC);
        #pragma unroll
        for (int t = 0; t < 4; t++) {
            wmma::fragment<wmma::matrix_b, 16, 16, 16, __half, wmma::row_major> bf;
            wmma::load_matrix_sync(bf, Bs + (k * 16) * CC + ch * 64 + t * 16, CC);
            wmma::mma_sync(accf[t], af, bf, accf[t]);
        }
    }
    __syncthreads();   // done with As/Bs

    #pragma unroll
    for (int t = 0; t < 4; t++)
        wmma::store_matrix_sync(Ob + (rt * 16) * CC + ch * 64 + t * 16,
                                accf[t], CC, wmma::mem_row_major);
    __syncthreads();

    // epilogue: Y = Ob + b_fc + X  (float4 per thread-iter, coalesced)
    for (int i = tid; i < YROWS * 32; i += 256) {
        const int r = i >> 5, c4 = i & 31;
        const int row = row0 + r;
        if (row >= BN) continue;
        const float4 ov = ((const float4*)Ob)[r * 32 + c4];
        const float4 bv = ((const float4*)b_fc)[c4];
        const float4 xv = ((const float4*)(X + (size_t)row * CC))[c4];
        ((float4*)(Y + (size_t)row * CC))[c4] =
            make_float4(ov.x + bv.x + xv.x, ov.y + bv.y + xv.y,
                        ov.z + bv.z + xv.z, ov.w + bv.w + xv.w);
    }
}

// ---------------------------------------------------------------------------
extern "C" void kernel_launch(void* const* d_in, const int* in_sizes, int n_in,
                              void* d_out, int out_size) {
    const float* X_B      = (const float*)d_in[0];
    const int*   esrc_bb  = (const int*)  d_in[1];
    const int*   edst_bb  = (const int*)  d_in[2];
    const float* ew_bb    = (const float*)d_in[3];
    const int*   esrc_bm  = (const int*)  d_in[4];
    const int*   edst_bm  = (const int*)  d_in[5];
    const float* ew_bm    = (const float*)d_in[6];
    const int*   c_idx    = (const int*)  d_in[7];
    const float* wr       = (const float*)d_in[8];
    const float* codebook = (const float*)d_in[9];
    const float* vq_grad  = (const float*)d_in[10];
    const float* W_conv   = (const float*)d_in[11];
    const float* b_conv   = (const float*)d_in[12];
    const float* W_fc     = (const float*)d_in[13];
    const float* b_fc     = (const float*)d_in[14];
    float* out = (float*)d_out;

    const int Ebb  = in_sizes[1];
    const int Ebm  = in_sizes[4];
    const int Etot = Ebb + Ebm;

    prep_kernel<<<(BN + 255) / 256, 256>>>(vq_grad, W_fc);
    fill_dst_kernel<<<(Etot + 255) / 256, 256>>>(esrc_bb, edst_bb, ew_bb,
                                                 esrc_bm, edst_bm, ew_bm,
                                                 c_idx, Ebb, Etot);
    vsum_kernel<<<(BN * 32 + 255) / 256, 256>>>();
    compute_h_kernel<<<(NODES + HROWS - 1) / HROWS, 256>>>(X_B, codebook, W_conv, wr);
    gather_kernel<<<(BN * 32 + 255) / 256, 256>>>(b_conv);
    finalize_kernel<<<1, 256>>>(vq_grad, b_conv, wr, out + (out_size - 1));
    y_kernel<<<(BN + YROWS - 1) / YROWS, 256>>>(X_B, b_fc, out);
}